// round 3
// baseline (speedup 1.0000x reference)
#include <cuda_runtime.h>
#include <math.h>
#include <stdint.h>

#define T_   256
#define B_   64
#define I_   256
#define H_   512
#define C_   64
#define G4H  2048
#define BH   (B_*H_)      // 32768
#define NCTA 136
#define NGEMM 128
#define NSYNC 512

// ---------------- static device scratch (no allocations allowed) ----------------
__device__ float    d_G[(size_t)T_ * B_ * G4H];     // 128 MB: input proj, then gates in-place
__device__ float    d_mem[(size_t)(T_ + 1) * BH];   // mem rows; mem[i+1] = h_out[i]
__device__ float    d_mseq[(size_t)T_ * BH];        // m_t per step
__device__ float    d_s2[(T_ + 1) * B_];            // cached memory scores
__device__ unsigned d_bar[NSYNC];                   // grid barrier slots

__device__ __forceinline__ float sigf(float x) { return 1.f / (1.f + __expf(-x)); }

// grid-wide barrier: one slot per sync, slots zeroed by reset kernel each launch
__device__ __forceinline__ void gsync(int slot, unsigned nct) {
    __threadfence();
    __syncthreads();
    if (threadIdx.x == 0) {
        atomicAdd(&d_bar[slot], 1u);
        while (*((volatile unsigned*)&d_bar[slot]) < nct) { }
        __threadfence();
    }
    __syncthreads();
}

// ---------------- reset: barriers, mem row 0, s2 row 0 ----------------
__global__ void reset_kernel() {
    int id = blockIdx.x * blockDim.x + threadIdx.x;   // 64*512 = 32768 threads
    d_mem[id] = 0.f;                                   // row 0 of mem (exactly 32768)
    if (id < NSYNC) d_bar[id] = 0u;
    if (id < B_)    d_s2[id] = 0.f;
}

// ---------------- K1: G = x @ W_ih^T + (b_ih + b_hh) ----------------
// M=16384 (t*64+b), N=2048, K=256.  64x64 tile, 256 threads, 4x4 micro.
__global__ void __launch_bounds__(256) gemm_ih_kernel(const float* __restrict__ X,
                                                      const float* __restrict__ Wih,
                                                      const float* __restrict__ bih,
                                                      const float* __restrict__ bhh) {
    __shared__ __align__(16) float a_s[16][64];
    __shared__ __align__(16) float b_s[16][64];
    int tx = threadIdx.x;
    int m0 = blockIdx.y * 64, n0 = blockIdx.x * 64;
    int tm = tx & 15, tn = tx >> 4;
    float acc[4][4];
#pragma unroll
    for (int r = 0; r < 4; r++)
#pragma unroll
        for (int c = 0; c < 4; c++) acc[r][c] = 0.f;

    int row = tx >> 2, qd = tx & 3;
    for (int k0 = 0; k0 < I_; k0 += 16) {
        float4 av = *(const float4*)(X + (size_t)(m0 + row) * I_ + k0 + qd * 4);
        float4 bv = *(const float4*)(Wih + (size_t)(n0 + row) * I_ + k0 + qd * 4);
        a_s[qd*4+0][row] = av.x; a_s[qd*4+1][row] = av.y; a_s[qd*4+2][row] = av.z; a_s[qd*4+3][row] = av.w;
        b_s[qd*4+0][row] = bv.x; b_s[qd*4+1][row] = bv.y; b_s[qd*4+2][row] = bv.z; b_s[qd*4+3][row] = bv.w;
        __syncthreads();
#pragma unroll
        for (int k = 0; k < 16; k++) {
            float4 a = *(const float4*)&a_s[k][tm * 4];
            float4 b = *(const float4*)&b_s[k][tn * 4];
            acc[0][0] = fmaf(a.x, b.x, acc[0][0]); acc[0][1] = fmaf(a.x, b.y, acc[0][1]);
            acc[0][2] = fmaf(a.x, b.z, acc[0][2]); acc[0][3] = fmaf(a.x, b.w, acc[0][3]);
            acc[1][0] = fmaf(a.y, b.x, acc[1][0]); acc[1][1] = fmaf(a.y, b.y, acc[1][1]);
            acc[1][2] = fmaf(a.y, b.z, acc[1][2]); acc[1][3] = fmaf(a.y, b.w, acc[1][3]);
            acc[2][0] = fmaf(a.z, b.x, acc[2][0]); acc[2][1] = fmaf(a.z, b.y, acc[2][1]);
            acc[2][2] = fmaf(a.z, b.z, acc[2][2]); acc[2][3] = fmaf(a.z, b.w, acc[2][3]);
            acc[3][0] = fmaf(a.w, b.x, acc[3][0]); acc[3][1] = fmaf(a.w, b.y, acc[3][1]);
            acc[3][2] = fmaf(a.w, b.z, acc[3][2]); acc[3][3] = fmaf(a.w, b.w, acc[3][3]);
        }
        __syncthreads();
    }
    float bias[4];
#pragma unroll
    for (int c = 0; c < 4; c++) {
        int n = n0 + tn * 4 + c;
        bias[c] = __ldg(bih + n) + __ldg(bhh + n);
    }
#pragma unroll
    for (int r = 0; r < 4; r++) {
        size_t m = (size_t)(m0 + tm * 4 + r);
        float4 o;
        o.x = acc[r][0] + bias[0]; o.y = acc[r][1] + bias[1];
        o.z = acc[r][2] + bias[2]; o.w = acc[r][3] + bias[3];
        *(float4*)(d_G + m * G4H + n0 + tn * 4) = o;
    }
}

// ---------------- K2: persistent recurrent kernel ----------------
// CTAs 0..127: per-step GEMM  gates[b][j] += h @ W_hh^T  (j-tile of 16 per CTA)
// CTAs 128..135: sparse attention (8 warps each -> 64 batches), pipelined vs GEMM
// Phase B: CTAs 0..63 (b = g): LSTM cell + h_out + mem/s2 update
__global__ void __launch_bounds__(256, 1) lstm_persistent(const float* __restrict__ W_hh,
                                                          const float* __restrict__ w_t) {
    __shared__ __align__(16) float h_s[64][66];
    __shared__ __align__(16) float w_s[64][18];
    __shared__ float red[8];
    __shared__ float wt2_s[H_];

    int g = blockIdx.x, tx = threadIdx.x;
    int lane = tx & 31, wrp = tx >> 5;
    int tb = tx & 31, tj = tx >> 5;

    if (g < B_) { wt2_s[tx] = w_t[H_ + tx]; wt2_s[tx + 256] = w_t[H_ + tx + 256]; }
    float cst0 = 0.f, cst1 = 0.f;   // cell state for h = tx, tx+256 (CTA g handles b = g)

    for (int i = 0; i < T_; ++i) {
        // ---------------- phase A ----------------
        if (g < NGEMM) {
            const float* hrow = d_mem + (size_t)i * BH;  // h_out[i-1] = mem[i]
            int j0 = g * 16;
            float a00 = 0.f, a01 = 0.f, a10 = 0.f, a11 = 0.f;
            for (int kc = 0; kc < H_; kc += 64) {
#pragma unroll
                for (int q = 0; q < 4; q++) {
                    int idx = tx + 256 * q;
                    int rw = idx >> 4, qd = idx & 15;
                    float4 hv = *(const float4*)(hrow + (size_t)rw * H_ + kc + qd * 4);
                    h_s[qd*4+0][rw] = hv.x; h_s[qd*4+1][rw] = hv.y;
                    h_s[qd*4+2][rw] = hv.z; h_s[qd*4+3][rw] = hv.w;
                }
                {
                    int j = tx >> 4, qd = tx & 15;
                    float4 wv = *(const float4*)(W_hh + (size_t)(j0 + j) * H_ + kc + qd * 4);
                    w_s[qd*4+0][j] = wv.x; w_s[qd*4+1][j] = wv.y;
                    w_s[qd*4+2][j] = wv.z; w_s[qd*4+3][j] = wv.w;
                }
                __syncthreads();
#pragma unroll 16
                for (int k = 0; k < 64; k++) {
                    float2 hv = *(const float2*)&h_s[k][2 * tb];
                    float2 wv = *(const float2*)&w_s[k][2 * tj];
                    a00 = fmaf(hv.x, wv.x, a00); a01 = fmaf(hv.x, wv.y, a01);
                    a10 = fmaf(hv.y, wv.x, a10); a11 = fmaf(hv.y, wv.y, a11);
                }
                __syncthreads();
            }
            float* Grow = d_G + (size_t)i * B_ * G4H;
            int b0 = 2 * tb, j = j0 + 2 * tj;
            float2* p0 = (float2*)(Grow + (size_t)b0 * G4H + j);
            float2 v0 = *p0; v0.x += a00; v0.y += a01; *p0 = v0;
            float2* p1 = (float2*)(Grow + (size_t)(b0 + 1) * G4H + j);
            float2 v1 = *p1; v1.x += a10; v1.y += a11; *p1 = v1;
        } else {
            // sparse attention for step i (uses only data finalized at step i-1)
            int b = (g - NGEMM) * 8 + wrp;    // one warp per batch
            int n = i + 1;                     // valid t in [0, i]
            float v[8];
            float mn = INFINITY;               // min over VALID scores only (ref uses +inf mask)
#pragma unroll
            for (int r = 0; r < 8; r++) {
                int t = lane + 32 * r;
                if (t < n) {
                    float s = __ldg(&d_s2[t * B_ + b]);
                    v[r] = s;
                    mn = fminf(mn, s);
                } else {
                    v[r] = -INFINITY;          // -inf mask for the top-k/max path
                }
            }
#pragma unroll
            for (int o = 16; o > 0; o >>= 1) mn = fminf(mn, __shfl_xor_sync(0xffffffffu, mn, o));
            float topv[5]; int topt[5];
#pragma unroll
            for (int k5 = 0; k5 < 5; k5++) {
                float bv = -INFINITY; int bt = 1 << 30;
#pragma unroll
                for (int r = 0; r < 8; r++) {
                    int t = lane + 32 * r;
                    if (v[r] > bv) { bv = v[r]; bt = t; }
                }
#pragma unroll
                for (int o = 16; o > 0; o >>= 1) {
                    float ov = __shfl_xor_sync(0xffffffffu, bv, o);
                    int   ot = __shfl_xor_sync(0xffffffffu, bt, o);
                    if (ov > bv || (ov == bv && ot < bt)) { bv = ov; bt = ot; }
                }
                topv[k5] = bv; topt[k5] = bt;
                int rr = bt >> 5;
                if ((bt & 31) == lane && rr >= 0 && rr < 8) v[rr] = -INFINITY;
            }
            // s1 cancels exactly: delta' = kth(s2) + eps (or min(s2)+eps when n<=5)
            float delta = ((n <= 5) ? mn : topv[4]) + 1e-7f;
            float wk[5]; float sum = 0.f;
#pragma unroll
            for (int k5 = 0; k5 < 5; k5++) { wk[k5] = fmaxf(topv[k5] - delta, 0.f); sum += wk[k5]; }
            float inv = 1.f / (sum + 1e-7f);
            float acc[16];
#pragma unroll
            for (int r = 0; r < 16; r++) acc[r] = 0.f;
#pragma unroll
            for (int k5 = 0; k5 < 5; k5++) {
                float wv = wk[k5] * inv;     // warp-uniform
                if (wv > 0.f) {
                    const float* rowp = d_mem + (size_t)topt[k5] * BH + (size_t)b * H_;
#pragma unroll
                    for (int r = 0; r < 16; r++) acc[r] = fmaf(wv, __ldg(rowp + lane + 32 * r), acc[r]);
                }
            }
            float* mrow = d_mseq + (size_t)i * BH + (size_t)b * H_;
#pragma unroll
            for (int r = 0; r < 16; r++) mrow[lane + 32 * r] = acc[r];
        }

        gsync(2 * i, NCTA);

        // ---------------- phase B: LSTM cell (CTA g handles batch b = g) ----------------
        if (g < B_) {
            int b = g;
            const float* Gr = d_G + ((size_t)i * B_ + b) * G4H;
            const float* mr = d_mseq + (size_t)i * BH + (size_t)b * H_;
            // gates row spans lines RMW'd by other SMs this step -> must bypass L1
            float gi0 = __ldcg(Gr + tx),        gi1 = __ldcg(Gr + tx + 256);
            float gf0 = __ldcg(Gr + 512 + tx),  gf1 = __ldcg(Gr + 512 + tx + 256);
            float gg0 = __ldcg(Gr + 1024 + tx), gg1 = __ldcg(Gr + 1024 + tx + 256);
            float go0 = __ldcg(Gr + 1536 + tx), go1 = __ldcg(Gr + 1536 + tx + 256);
            float m0 = __ldcg(mr + tx), m1 = __ldcg(mr + tx + 256);

            float cn0 = sigf(gf0) * cst0 + sigf(gi0) * tanhf(gg0);
            float cn1 = sigf(gf1) * cst1 + sigf(gi1) * tanhf(gg1);
            float hn0 = sigf(go0) * tanhf(cn0);
            float hn1 = sigf(go1) * tanhf(cn1);
            cst0 = cn0; cst1 = cn1;
            float ho0 = hn0 + m0, ho1 = hn1 + m1;

            float* memw = d_mem + (size_t)(i + 1) * BH + (size_t)b * H_;
            memw[tx] = ho0; memw[tx + 256] = ho1;

            float part = tanhf(ho0) * wt2_s[tx] + tanhf(ho1) * wt2_s[tx + 256];
#pragma unroll
            for (int o = 16; o > 0; o >>= 1) part += __shfl_xor_sync(0xffffffffu, part, o);
            if (lane == 0) red[wrp] = part;
            __syncthreads();
            if (wrp == 0) {
                float s = (lane < 8) ? red[lane] : 0.f;
#pragma unroll
                for (int o = 4; o > 0; o >>= 1) s += __shfl_xor_sync(0xffffffffu, s, o);
                if (lane == 0) d_s2[(i + 1) * B_ + b] = s;
            }
        }

        gsync(2 * i + 1, NCTA);
    }
}

// ---------------- K3: out = [h_seq | m_seq] @ fc_w^T + fc_b ----------------
// M=16384, N=64, K=1024.  64x64 tile per CTA (N fully covered), 256 CTAs.
__global__ void __launch_bounds__(256) fc_final_kernel(const float* __restrict__ fcw,
                                                       const float* __restrict__ fcb,
                                                       float* __restrict__ out) {
    __shared__ __align__(16) float a_s[16][64];
    __shared__ __align__(16) float b_s[16][64];
    int tx = threadIdx.x;
    int m0 = blockIdx.x * 64;
    int tm = tx & 15, tn = tx >> 4;
    float acc[4][4];
#pragma unroll
    for (int r = 0; r < 4; r++)
#pragma unroll
        for (int c = 0; c < 4; c++) acc[r][c] = 0.f;

    int row = tx >> 2, qd = tx & 3;
    int m = m0 + row, t = m >> 6, b = m & 63;
    for (int k0 = 0; k0 < 2 * H_; k0 += 16) {
        int k = k0 + qd * 4;
        const float* src = (k < H_)
            ? (d_mem + ((size_t)(t + 1) * B_ + b) * H_ + k)         // h_seq[t] = mem[t+1]
            : (d_mseq + ((size_t)t * B_ + b) * H_ + (k - H_));       // m_seq[t]
        float4 av = *(const float4*)src;
        float4 bv = *(const float4*)(fcw + (size_t)row * (2 * H_) + k);
        a_s[qd*4+0][row] = av.x; a_s[qd*4+1][row] = av.y; a_s[qd*4+2][row] = av.z; a_s[qd*4+3][row] = av.w;
        b_s[qd*4+0][row] = bv.x; b_s[qd*4+1][row] = bv.y; b_s[qd*4+2][row] = bv.z; b_s[qd*4+3][row] = bv.w;
        __syncthreads();
#pragma unroll
        for (int k2 = 0; k2 < 16; k2++) {
            float4 a = *(const float4*)&a_s[k2][tm * 4];
            float4 bb = *(const float4*)&b_s[k2][tn * 4];
            acc[0][0] = fmaf(a.x, bb.x, acc[0][0]); acc[0][1] = fmaf(a.x, bb.y, acc[0][1]);
            acc[0][2] = fmaf(a.x, bb.z, acc[0][2]); acc[0][3] = fmaf(a.x, bb.w, acc[0][3]);
            acc[1][0] = fmaf(a.y, bb.x, acc[1][0]); acc[1][1] = fmaf(a.y, bb.y, acc[1][1]);
            acc[1][2] = fmaf(a.y, bb.z, acc[1][2]); acc[1][3] = fmaf(a.y, bb.w, acc[1][3]);
            acc[2][0] = fmaf(a.z, bb.x, acc[2][0]); acc[2][1] = fmaf(a.z, bb.y, acc[2][1]);
            acc[2][2] = fmaf(a.z, bb.z, acc[2][2]); acc[2][3] = fmaf(a.z, bb.w, acc[2][3]);
            acc[3][0] = fmaf(a.w, bb.x, acc[3][0]); acc[3][1] = fmaf(a.w, bb.y, acc[3][1]);
            acc[3][2] = fmaf(a.w, bb.z, acc[3][2]); acc[3][3] = fmaf(a.w, bb.w, acc[3][3]);
        }
        __syncthreads();
    }
    float bias[4];
#pragma unroll
    for (int c = 0; c < 4; c++) bias[c] = __ldg(fcb + tn * 4 + c);
#pragma unroll
    for (int r = 0; r < 4; r++) {
        size_t mm = (size_t)(m0 + tm * 4 + r);
        float4 o;
        o.x = acc[r][0] + bias[0]; o.y = acc[r][1] + bias[1];
        o.z = acc[r][2] + bias[2]; o.w = acc[r][3] + bias[3];
        *(float4*)(out + mm * C_ + tn * 4) = o;
    }
}

// ---------------- launch ----------------
extern "C" void kernel_launch(void* const* d_in, const int* in_sizes, int n_in,
                              void* d_out, int out_size) {
    const float* x    = (const float*)d_in[0];
    const float* W_ih = (const float*)d_in[1];
    const float* W_hh = (const float*)d_in[2];
    const float* b_ih = (const float*)d_in[3];
    const float* b_hh = (const float*)d_in[4];
    const float* w_t  = (const float*)d_in[5];
    const float* fc_w = (const float*)d_in[6];
    const float* fc_b = (const float*)d_in[7];
    float* out = (float*)d_out;

    reset_kernel<<<64, 512>>>();
    gemm_ih_kernel<<<dim3(G4H / 64, (T_ * B_) / 64), 256>>>(x, W_ih, b_ih, b_hh);
    lstm_persistent<<<NCTA, 256>>>(W_hh, w_t);
    fc_final_kernel<<<(T_ * B_) / 64, 256>>>(fc_w, fc_b, out);
}

// round 4
// speedup vs baseline: 1.4148x; 1.4148x over previous
#include <cuda_runtime.h>
#include <math.h>
#include <stdint.h>

#define T_   256
#define B_   64
#define I_   256
#define H_   512
#define C_   64
#define G4H  2048
#define BH   (B_*H_)      // 32768
#define NCTA 136
#define NGEMM 128
#define NATT_CTA 8
#define NSYNC 256

// smem layout for GEMM CTAs (floats)
#define WS_ELE (512*64)       // persistent W tile, k-major [k][jj]
#define HS_ELE (512*18)       // h tile [k][b_local], pad 18
#define GS_ELE (16*68)        // gate staging [b_local][jj], pad 68
#define SMEM_FLOATS (WS_ELE + HS_ELE + GS_ELE)
#define SMEM_BYTES  (SMEM_FLOATS * 4)

// ---------------- static device scratch ----------------
__device__ float    d_G[(size_t)T_ * B_ * G4H];     // input proj + biases (read-only in lstm)
__device__ float    d_mem[(size_t)(T_ + 1) * BH];   // mem rows; mem[i+1] = h_out[i]
__device__ float    d_mseq[(size_t)T_ * BH];        // m_t per step
__device__ float    d_s2[B_ * (T_ + 1)];            // cached memory scores, [b][t]
__device__ unsigned d_bar[NSYNC];                   // grid barrier slots
__device__ unsigned d_aflag[NSYNC];                 // attention-done flags

__device__ __forceinline__ float sigf(float x) { return 1.f / (1.f + __expf(-x)); }

__device__ __forceinline__ void gsync(int slot, unsigned nct) {
    __threadfence();
    __syncthreads();
    if (threadIdx.x == 0) {
        atomicAdd(&d_bar[slot], 1u);
        while (*((volatile unsigned*)&d_bar[slot]) < nct) { }
        __threadfence();
    }
    __syncthreads();
}

// ---------------- reset ----------------
__global__ void reset_kernel() {
    int id = blockIdx.x * blockDim.x + threadIdx.x;   // 32768 threads
    d_mem[id] = 0.f;                                   // mem row 0
    if (id < B_ * (T_ + 1)) d_s2[id] = 0.f;
    if (id < NSYNC) { d_bar[id] = 0u; d_aflag[id] = 0u; }
}

// ---------------- K1: G = x @ W_ih^T + (b_ih + b_hh) ----------------
__global__ void __launch_bounds__(256) gemm_ih_kernel(const float* __restrict__ X,
                                                      const float* __restrict__ Wih,
                                                      const float* __restrict__ bih,
                                                      const float* __restrict__ bhh) {
    __shared__ __align__(16) float a_s[16][64];
    __shared__ __align__(16) float b_s[16][64];
    int tx = threadIdx.x;
    int m0 = blockIdx.y * 64, n0 = blockIdx.x * 64;
    int tm = tx & 15, tn = tx >> 4;
    float acc[4][4];
#pragma unroll
    for (int r = 0; r < 4; r++)
#pragma unroll
        for (int c = 0; c < 4; c++) acc[r][c] = 0.f;

    int row = tx >> 2, qd = tx & 3;
    for (int k0 = 0; k0 < I_; k0 += 16) {
        float4 av = *(const float4*)(X + (size_t)(m0 + row) * I_ + k0 + qd * 4);
        float4 bv = *(const float4*)(Wih + (size_t)(n0 + row) * I_ + k0 + qd * 4);
        a_s[qd*4+0][row] = av.x; a_s[qd*4+1][row] = av.y; a_s[qd*4+2][row] = av.z; a_s[qd*4+3][row] = av.w;
        b_s[qd*4+0][row] = bv.x; b_s[qd*4+1][row] = bv.y; b_s[qd*4+2][row] = bv.z; b_s[qd*4+3][row] = bv.w;
        __syncthreads();
#pragma unroll
        for (int k = 0; k < 16; k++) {
            float4 a = *(const float4*)&a_s[k][tm * 4];
            float4 b = *(const float4*)&b_s[k][tn * 4];
            acc[0][0] = fmaf(a.x, b.x, acc[0][0]); acc[0][1] = fmaf(a.x, b.y, acc[0][1]);
            acc[0][2] = fmaf(a.x, b.z, acc[0][2]); acc[0][3] = fmaf(a.x, b.w, acc[0][3]);
            acc[1][0] = fmaf(a.y, b.x, acc[1][0]); acc[1][1] = fmaf(a.y, b.y, acc[1][1]);
            acc[1][2] = fmaf(a.y, b.z, acc[1][2]); acc[1][3] = fmaf(a.y, b.w, acc[1][3]);
            acc[2][0] = fmaf(a.z, b.x, acc[2][0]); acc[2][1] = fmaf(a.z, b.y, acc[2][1]);
            acc[2][2] = fmaf(a.z, b.z, acc[2][2]); acc[2][3] = fmaf(a.z, b.w, acc[2][3]);
            acc[3][0] = fmaf(a.w, b.x, acc[3][0]); acc[3][1] = fmaf(a.w, b.y, acc[3][1]);
            acc[3][2] = fmaf(a.w, b.z, acc[3][2]); acc[3][3] = fmaf(a.w, b.w, acc[3][3]);
        }
        __syncthreads();
    }
    float bias[4];
#pragma unroll
    for (int c = 0; c < 4; c++) {
        int n = n0 + tn * 4 + c;
        bias[c] = __ldg(bih + n) + __ldg(bhh + n);
    }
#pragma unroll
    for (int r = 0; r < 4; r++) {
        size_t m = (size_t)(m0 + tm * 4 + r);
        float4 o;
        o.x = acc[r][0] + bias[0]; o.y = acc[r][1] + bias[1];
        o.z = acc[r][2] + bias[2]; o.w = acc[r][3] + bias[3];
        *(float4*)(d_G + m * G4H + n0 + tn * 4) = o;
    }
}

// ---------------- K2: fused persistent recurrent kernel ----------------
// CTAs 0..127: (jg = g>>2, bg = g&3). Own (16 b x 16 h) block: GEMM for its
//   64 gate cols {q*512 + h0 + c}, then LSTM cell in-register. W tile persistent in smem.
// CTAs 128..135: sparse attention (warp per batch), concurrent with GEMM; flag handoff.
// One grid barrier per step.
__global__ void __launch_bounds__(256, 1) lstm_persistent(const float* __restrict__ W_hh,
                                                          const float* __restrict__ w_t) {
    extern __shared__ __align__(16) float smem[];
    float* w_s  = smem;                 // [k][jj]  stride 64
    float* h_s  = smem + WS_ELE;        // [k][bl]  stride 18
    float* g_sm = smem + WS_ELE + HS_ELE; // [bl][jj] stride 68

    int g = blockIdx.x, tx = threadIdx.x;
    int wrp = tx >> 5, lane = tx & 31;

    if (g < NGEMM) {
        int jg = g >> 2, bg = g & 3;
        int h0 = jg * 16;

        // ---- stage W tile once (persistent across all steps) ----
#pragma unroll
        for (int q2 = 0; q2 < 32; q2++) {
            int it = q2 * 256 + tx;            // [0, 8192) float4s
            int kq2 = it & 3;
            int jj3 = (it >> 2) & 7;
            int rest = it >> 5;                 // [0,256)
            int jj = jj3 | ((rest & 7) << 3);   // [0,64)
            int kq = kq2 | ((rest >> 3) << 2);  // [0,128)
            int q = jj >> 4, c = jj & 15;
            float4 v = __ldg((const float4*)(W_hh + (size_t)(q * H_ + h0 + c) * H_ + kq * 4));
            w_s[(kq*4+0)*64 + jj] = v.x;
            w_s[(kq*4+1)*64 + jj] = v.y;
            w_s[(kq*4+2)*64 + jj] = v.z;
            w_s[(kq*4+3)*64 + jj] = v.w;
        }
        __syncthreads();

        // GEMM thread mapping: warp covers 4 b x 32 jj
        int bp = lane >> 4, jp = lane & 15;
        int Bw = (wrp & 3) * 4 + bp * 2;        // local b pair base (even)
        int Jw = (wrp >> 2) * 32 + jp * 2;      // jj pair base (even)
        int qj = Jw >> 4, cj = Jw & 15;
        size_t gcol = (size_t)qj * H_ + h0 + cj; // actual gate column of Jw

        // epilogue thread mapping: one (b,h) cell per thread
        int bl = tx >> 4, hi = tx & 15;
        float wt2v = __ldg(w_t + H_ + h0 + hi);
        float cstate = 0.f;

        for (int i = 0; i < T_; ++i) {
            // ---- stage h tile: mem[i][bg*16 .. +15][0..511] ----
            const float* hrow = d_mem + (size_t)i * BH + (size_t)bg * 16 * H_;
#pragma unroll
            for (int q2 = 0; q2 < 8; q2++) {
                int it = q2 * 256 + tx;         // [0,2048) float4s, b fast
                int b = it & 15, kq = it >> 4;  // kq in [0,128)
                float4 v = __ldcg((const float4*)(hrow + (size_t)b * H_ + kq * 4));
                h_s[(kq*4+0)*18 + b] = v.x;
                h_s[(kq*4+1)*18 + b] = v.y;
                h_s[(kq*4+2)*18 + b] = v.z;
                h_s[(kq*4+3)*18 + b] = v.w;
            }
            __syncthreads();

            // ---- acc init from precomputed input projection ----
            const float* gp = d_G + ((size_t)i * B_ + bg * 16 + Bw) * G4H + gcol;
            float2 t0 = __ldcg((const float2*)gp);
            float2 t1 = __ldcg((const float2*)(gp + G4H));
            float a00 = t0.x, a01 = t0.y, a10 = t1.x, a11 = t1.y;

            // ---- k loop ----
#pragma unroll 8
            for (int k = 0; k < H_; k++) {
                float2 hv = *(const float2*)&h_s[k * 18 + Bw];
                float2 wv = *(const float2*)&w_s[k * 64 + Jw];
                a00 = fmaf(hv.x, wv.x, a00); a01 = fmaf(hv.x, wv.y, a01);
                a10 = fmaf(hv.y, wv.x, a10); a11 = fmaf(hv.y, wv.y, a11);
            }

            // ---- stage gates to smem ----
            *(float2*)&g_sm[Bw * 68 + Jw]       = make_float2(a00, a01);
            *(float2*)&g_sm[(Bw + 1) * 68 + Jw] = make_float2(a10, a11);

            // ---- wait for attention m_t of this step ----
            if (tx == 0) {
                volatile unsigned* fl = (volatile unsigned*)d_aflag;
                while (fl[i] < (unsigned)NATT_CTA) { }
            }
            __syncthreads();

            // ---- LSTM cell for (b = bg*16+bl, h = h0+hi) ----
            {
                float gi = g_sm[bl * 68 + hi];
                float gf = g_sm[bl * 68 + 16 + hi];
                float gg = g_sm[bl * 68 + 32 + hi];
                float go = g_sm[bl * 68 + 48 + hi];
                size_t off = (size_t)(bg * 16 + bl) * H_ + h0 + hi;
                float mt = __ldcg(d_mseq + (size_t)i * BH + off);

                float cn = sigf(gf) * cstate + sigf(gi) * tanhf(gg);
                float hn = sigf(go) * tanhf(cn);
                cstate = cn;
                float ho = hn + mt;

                d_mem[(size_t)(i + 1) * BH + off] = ho;

                float part = tanhf(ho) * wt2v;
#pragma unroll
                for (int o = 8; o > 0; o >>= 1) part += __shfl_xor_sync(0xffffffffu, part, o);
                if ((lane & 15) == 0)
                    atomicAdd(&d_s2[(bg * 16 + bl) * (T_ + 1) + (i + 1)], part);
            }

            gsync(i, NCTA);
        }
    } else {
        // ---------------- attention CTAs ----------------
        int b = (g - NGEMM) * 8 + wrp;          // one warp per batch
        for (int i = 0; i < T_; ++i) {
            int n = i + 1;                       // valid t in [0, i]
            float v[8];
            float mn = INFINITY;                 // min over VALID scores only
#pragma unroll
            for (int r = 0; r < 8; r++) {
                int t = lane + 32 * r;
                if (t < n) {
                    float s = __ldcg(d_s2 + b * (T_ + 1) + t);
                    v[r] = s;
                    mn = fminf(mn, s);
                } else {
                    v[r] = -INFINITY;
                }
            }
#pragma unroll
            for (int o = 16; o > 0; o >>= 1) mn = fminf(mn, __shfl_xor_sync(0xffffffffu, mn, o));
            float topv[5]; int topt[5];
#pragma unroll
            for (int k5 = 0; k5 < 5; k5++) {
                float bv = -INFINITY; int bt = 1 << 30;
#pragma unroll
                for (int r = 0; r < 8; r++) {
                    int t = lane + 32 * r;
                    if (v[r] > bv) { bv = v[r]; bt = t; }
                }
#pragma unroll
                for (int o = 16; o > 0; o >>= 1) {
                    float ov = __shfl_xor_sync(0xffffffffu, bv, o);
                    int   ot = __shfl_xor_sync(0xffffffffu, bt, o);
                    if (ov > bv || (ov == bv && ot < bt)) { bv = ov; bt = ot; }
                }
                topv[k5] = bv; topt[k5] = bt;
                int rr = bt >> 5;
                if ((bt & 31) == lane && rr >= 0 && rr < 8) v[rr] = -INFINITY;
            }
            float delta = ((n <= 5) ? mn : topv[4]) + 1e-7f;
            float wk[5]; float sum = 0.f;
#pragma unroll
            for (int k5 = 0; k5 < 5; k5++) { wk[k5] = fmaxf(topv[k5] - delta, 0.f); sum += wk[k5]; }
            float inv = 1.f / (sum + 1e-7f);
            float acc[16];
#pragma unroll
            for (int r = 0; r < 16; r++) acc[r] = 0.f;
#pragma unroll
            for (int k5 = 0; k5 < 5; k5++) {
                float wv = wk[k5] * inv;         // warp-uniform
                if (wv > 0.f) {
                    const float* rowp = d_mem + (size_t)topt[k5] * BH + (size_t)b * H_;
#pragma unroll
                    for (int r = 0; r < 16; r++) acc[r] = fmaf(wv, __ldg(rowp + lane + 32 * r), acc[r]);
                }
            }
            float* mrow = d_mseq + (size_t)i * BH + (size_t)b * H_;
#pragma unroll
            for (int r = 0; r < 16; r++) mrow[lane + 32 * r] = acc[r];

            // publish: m_t for step i is ready
            __threadfence();
            __syncthreads();
            if (tx == 0) atomicAdd(&d_aflag[i], 1u);

            gsync(i, NCTA);
        }
    }
}

// ---------------- K3: out = [h_seq | m_seq] @ fc_w^T + fc_b ----------------
__global__ void __launch_bounds__(256) fc_final_kernel(const float* __restrict__ fcw,
                                                       const float* __restrict__ fcb,
                                                       float* __restrict__ out) {
    __shared__ __align__(16) float a_s[16][64];
    __shared__ __align__(16) float b_s[16][64];
    int tx = threadIdx.x;
    int m0 = blockIdx.x * 64;
    int tm = tx & 15, tn = tx >> 4;
    float acc[4][4];
#pragma unroll
    for (int r = 0; r < 4; r++)
#pragma unroll
        for (int c = 0; c < 4; c++) acc[r][c] = 0.f;

    int row = tx >> 2, qd = tx & 3;
    int m = m0 + row, t = m >> 6, b = m & 63;
    for (int k0 = 0; k0 < 2 * H_; k0 += 16) {
        int k = k0 + qd * 4;
        const float* src = (k < H_)
            ? (d_mem + ((size_t)(t + 1) * B_ + b) * H_ + k)
            : (d_mseq + ((size_t)t * B_ + b) * H_ + (k - H_));
        float4 av = *(const float4*)src;
        float4 bv = *(const float4*)(fcw + (size_t)row * (2 * H_) + k);
        a_s[qd*4+0][row] = av.x; a_s[qd*4+1][row] = av.y; a_s[qd*4+2][row] = av.z; a_s[qd*4+3][row] = av.w;
        b_s[qd*4+0][row] = bv.x; b_s[qd*4+1][row] = bv.y; b_s[qd*4+2][row] = bv.z; b_s[qd*4+3][row] = bv.w;
        __syncthreads();
#pragma unroll
        for (int k2 = 0; k2 < 16; k2++) {
            float4 a = *(const float4*)&a_s[k2][tm * 4];
            float4 bb = *(const float4*)&b_s[k2][tn * 4];
            acc[0][0] = fmaf(a.x, bb.x, acc[0][0]); acc[0][1] = fmaf(a.x, bb.y, acc[0][1]);
            acc[0][2] = fmaf(a.x, bb.z, acc[0][2]); acc[0][3] = fmaf(a.x, bb.w, acc[0][3]);
            acc[1][0] = fmaf(a.y, bb.x, acc[1][0]); acc[1][1] = fmaf(a.y, bb.y, acc[1][1]);
            acc[1][2] = fmaf(a.y, bb.z, acc[1][2]); acc[1][3] = fmaf(a.y, bb.w, acc[1][3]);
            acc[2][0] = fmaf(a.z, bb.x, acc[2][0]); acc[2][1] = fmaf(a.z, bb.y, acc[2][1]);
            acc[2][2] = fmaf(a.z, bb.z, acc[2][2]); acc[2][3] = fmaf(a.z, bb.w, acc[2][3]);
            acc[3][0] = fmaf(a.w, bb.x, acc[3][0]); acc[3][1] = fmaf(a.w, bb.y, acc[3][1]);
            acc[3][2] = fmaf(a.w, bb.z, acc[3][2]); acc[3][3] = fmaf(a.w, bb.w, acc[3][3]);
        }
        __syncthreads();
    }
    float bias[4];
#pragma unroll
    for (int c = 0; c < 4; c++) bias[c] = __ldg(fcb + tn * 4 + c);
#pragma unroll
    for (int r = 0; r < 4; r++) {
        size_t mm = (size_t)(m0 + tm * 4 + r);
        float4 o;
        o.x = acc[r][0] + bias[0]; o.y = acc[r][1] + bias[1];
        o.z = acc[r][2] + bias[2]; o.w = acc[r][3] + bias[3];
        *(float4*)(out + mm * C_ + tn * 4) = o;
    }
}

// ---------------- launch ----------------
extern "C" void kernel_launch(void* const* d_in, const int* in_sizes, int n_in,
                              void* d_out, int out_size) {
    const float* x    = (const float*)d_in[0];
    const float* W_ih = (const float*)d_in[1];
    const float* W_hh = (const float*)d_in[2];
    const float* b_ih = (const float*)d_in[3];
    const float* b_hh = (const float*)d_in[4];
    const float* w_t  = (const float*)d_in[5];
    const float* fc_w = (const float*)d_in[6];
    const float* fc_b = (const float*)d_in[7];
    float* out = (float*)d_out;

    static int smem_set = 0;
    if (!smem_set) {
        cudaFuncSetAttribute(lstm_persistent,
                             cudaFuncAttributeMaxDynamicSharedMemorySize, SMEM_BYTES);
        smem_set = 1;
    }

    reset_kernel<<<64, 512>>>();
    gemm_ih_kernel<<<dim3(G4H / 64, (T_ * B_) / 64), 256>>>(x, W_ih, b_ih, b_hh);
    lstm_persistent<<<NCTA, 256, SMEM_BYTES>>>(W_hh, w_t);
    fc_final_kernel<<<(T_ * B_) / 64, 256>>>(fc_w, fc_b, out);
}